// round 15
// baseline (speedup 1.0000x reference)
#include <cuda_runtime.h>
#include <cstddef>

#define BATCH 8
#define HW 512
#define NLEV 9

// Pyramid scratch for levels 1..5 (6,7,8 staged in smem by up), NHWC (C=2).
__device__ __align__(16) float g_pyr[1398080];

// float offsets of level l inside g_pyr; index 0 unused.
__constant__ int c_off[9] = {0, 0, 1048576, 1310720, 1376256, 1392640, 1396736, 1397760, 1398016};

// ---------------------------------------------------------------------------
// pool_all: ONE kernel builds the whole pyramid (levels 1..5) AND emits the
// level-0 transposed output planes. Block = (batch, h-stripe p of 16).
__global__ __launch_bounds__(512) void pool_all_kernel(const float* __restrict__ x,
                                                       float* __restrict__ out) {
    const int p = blockIdx.x & 15;
    const int b = blockIdx.x >> 4;

    // Phase A: input -> level 1 (rows 16p..16p+15), plus level-0 output copy.
    for (int i = threadIdx.x; i < 16 * 128; i += 512) {
        int wp = i & 127;
        int hd = p * 16 + (i >> 7);
        int wd = wp * 2;
        int ws = wd * 2;
        int hs0 = 2 * hd, hs1 = 2 * hd + 1;

        const float4* r0 = (const float4*)(x + ((size_t)(b * HW + hs0) * HW + ws) * 2);
        const float4* r1 = (const float4*)((const float*)r0 + (size_t)HW * 2);
        float4 a0 = r0[0], a1 = r0[1];
        float4 c0 = r1[0], c1 = r1[1];

        float4 pv;
        pv.x = (a0.x + a0.z + c0.x + c0.z) * 0.25f;
        pv.y = (a0.y + a0.w + c0.y + c0.w) * 0.25f;
        pv.z = (a1.x + a1.z + c1.x + c1.z) * 0.25f;
        pv.w = (a1.y + a1.w + c1.y + c1.w) * 0.25f;
        *(float4*)(g_pyr + ((size_t)(b * 256 + hd) * 256 + wd) * 2) = pv;

        float* o00 = out + (((size_t)(b * 2 * NLEV + 0) * HW + hs0) * HW + ws);
        float* o01 = o00 + (size_t)HW;
        float* o10 = out + (((size_t)(b * 2 * NLEV + 1) * HW + hs0) * HW + ws);
        float* o11 = o10 + (size_t)HW;
        *(float4*)o00 = make_float4(a0.x, a0.z, a1.x, a1.z);
        *(float4*)o01 = make_float4(c0.x, c0.z, c1.x, c1.z);
        *(float4*)o10 = make_float4(a0.y, a0.w, a1.y, a1.w);
        *(float4*)o11 = make_float4(c0.y, c0.w, c1.y, c1.w);
    }
    __syncthreads();

    // Phase B: chain levels 1->2->3->4->5 within the stripe.
#pragma unroll
    for (int l = 1; l <= 4; ++l) {
        const int Ss = HW >> l;
        const int Sd = Ss >> 1;
        const int rows = Sd >> 4;
        const float* src = g_pyr + c_off[l]     + (size_t)b * Ss * Ss * 2;
        float*       dst = g_pyr + c_off[l + 1] + (size_t)b * Sd * Sd * 2;
        const int r0 = p * rows;
        const int n = rows * Sd;
        for (int i = threadIdx.x; i < n; i += 512) {
            int wd = i % Sd;
            int hd = r0 + i / Sd;
            float4 a = *(const float4*)(src + ((size_t)(2 * hd) * Ss + 2 * wd) * 2);
            float4 c = *(const float4*)(src + ((size_t)(2 * hd + 1) * Ss + 2 * wd) * 2);
            float2 o;
            o.x = (a.x + a.z + c.x + c.z) * 0.25f;
            o.y = (a.y + a.w + c.y + c.w) * 0.25f;
            *(float2*)(dst + ((size_t)hd * Sd + wd) * 2) = o;
        }
        __syncthreads();
    }
}

// ---------------------------------------------------------------------------
// smem staging helpers: pool from level-5 (16x16, L2-resident broadcast reads)
__device__ __forceinline__ float2 pool2x2(const float* base, int S, int ih, int iw) {
    float4 a = *(const float4*)(base + ((size_t)(2 * ih) * S + 2 * iw) * 2);
    float4 c = *(const float4*)(base + ((size_t)(2 * ih + 1) * S + 2 * iw) * 2);
    return make_float2((a.x + a.z + c.x + c.z) * 0.25f,
                       (a.y + a.w + c.y + c.w) * 0.25f);
}
__device__ __forceinline__ float2 pool4x4(const float* base, int S, int ih, int iw) {
    float sx = 0.f, sy = 0.f;
#pragma unroll
    for (int rr = 0; rr < 4; ++rr) {
        float4 q0 = *(const float4*)(base + ((size_t)(4 * ih + rr) * S + 4 * iw) * 2);
        float4 q1 = *(const float4*)(base + ((size_t)(4 * ih + rr) * S + 4 * iw + 2) * 2);
        sx += q0.x + q0.z + q1.x + q1.z;
        sy += q0.y + q0.w + q1.y + q1.w;
    }
    return make_float2(sx * 0.0625f, sy * 0.0625f);
}

__device__ __forceinline__ float2 shfl_up2(float2 v) {
    float2 r;
    r.x = __shfl_up_sync(0xffffffffu, v.x, 1);
    r.y = __shfl_up_sync(0xffffffffu, v.y, 1);
    return r;
}
__device__ __forceinline__ float2 shfl_down2(float2 v) {
    float2 r;
    r.x = __shfl_down_sync(0xffffffffu, v.x, 1);
    r.y = __shfl_down_sync(0xffffffffu, v.y, 1);
    return r;
}

// ---------------------------------------------------------------------------
// up_body: 8 consecutive w outputs per thread, both channels.
// L<=3: coalesced owned-column loads + warp-shuffle halo exchange.
// L>=4: 8 outputs straddle <=2 columns (generic gather, cheap).
template <int L>
__device__ __forceinline__ void up_body(float* __restrict__ out,
                                        const float2* __restrict__ src2,
                                        int b, int h) {
    const int t = threadIdx.x;            // 0..63
    const int w = t * 8;
    float* out0 = out + (((size_t)(b * 2 * NLEV + 2 * L) * HW + h) * HW + w);
    float* out1 = out0 + (size_t)HW * HW;

    constexpr int F = 1 << L;
    constexpr int S = HW >> L;
    constexpr float INV = 1.0f / F;

    float sfh = (h + 0.5f) * INV - 0.5f;
    int   ifh = (int)floorf(sfh);
    float fh  = sfh - (float)ifh;
    int ih0 = min(max(ifh, 0), S - 1);
    int ih1 = min(max(ifh + 1, 0), S - 1);
    const float wy0 = 1.0f - fh;
    const float2* r0 = src2 + (size_t)ih0 * S;
    const float2* r1 = src2 + (size_t)ih1 * S;

    float po0[8];
    float po1[8];

    if constexpr (L <= 3) {
        constexpr int NF = 8 >> L;            // owned columns: 4,2,1
        constexpr int OFF1[8] = {0,1,1,2,2,3,3,4};
        constexpr int OFF2[8] = {0,0,1,1,1,1,2,2};
        constexpr int OFF3[8] = {0,0,0,0,1,1,1,1};
        constexpr float FW1[8] = {0.75f,0.25f,0.75f,0.25f,0.75f,0.25f,0.75f,0.25f};
        constexpr float FW2[8] = {0.625f,0.875f,0.125f,0.375f,0.625f,0.875f,0.125f,0.375f};
        constexpr float FW3[8] = {0.5625f,0.6875f,0.8125f,0.9375f,0.0625f,0.1875f,0.3125f,0.4375f};
        const int lane = t & 31;
        const int cbase = t * NF;

        // a[0]=halo-left, a[1..NF]=owned cols cbase..cbase+NF-1, a[NF+1]=halo-right
        float2 a0[NF + 2], a1[NF + 2];
        if constexpr (NF == 4) {
            float4 q0 = ((const float4*)r0)[t * 2], q0b = ((const float4*)r0)[t * 2 + 1];
            float4 q1 = ((const float4*)r1)[t * 2], q1b = ((const float4*)r1)[t * 2 + 1];
            a0[1] = make_float2(q0.x, q0.y);  a0[2] = make_float2(q0.z, q0.w);
            a0[3] = make_float2(q0b.x, q0b.y); a0[4] = make_float2(q0b.z, q0b.w);
            a1[1] = make_float2(q1.x, q1.y);  a1[2] = make_float2(q1.z, q1.w);
            a1[3] = make_float2(q1b.x, q1b.y); a1[4] = make_float2(q1b.z, q1b.w);
        } else if constexpr (NF == 2) {
            float4 q0 = ((const float4*)r0)[t];
            float4 q1 = ((const float4*)r1)[t];
            a0[1] = make_float2(q0.x, q0.y);  a0[2] = make_float2(q0.z, q0.w);
            a1[1] = make_float2(q1.x, q1.y);  a1[2] = make_float2(q1.z, q1.w);
        } else {
            a0[1] = r0[t];
            a1[1] = r1[t];
        }
        // halo exchange: left = neighbor lane's last owned col, right = next lane's first
        a0[0]      = shfl_up2(a0[NF]);
        a1[0]      = shfl_up2(a1[NF]);
        a0[NF + 1] = shfl_down2(a0[1]);
        a1[NF + 1] = shfl_down2(a1[1]);
        if (lane == 0) {                      // cross-warp / global-left edge
            int ci = max(cbase - 1, 0);
            a0[0] = r0[ci];
            a1[0] = r1[ci];
        }
        if (lane == 31) {                     // cross-warp / global-right edge
            int ci = min(cbase + NF, S - 1);
            a0[NF + 1] = r0[ci];
            a1[NF + 1] = r1[ci];
        }

#pragma unroll
        for (int k = 0; k < 8; ++k) {
            const int   off = (L == 1) ? OFF1[k] : (L == 2) ? OFF2[k] : OFF3[k];
            const float fw  = (L == 1) ? FW1[k]  : (L == 2) ? FW2[k]  : FW3[k];
            const float wx0 = 1.0f - fw;
            float2 v00 = a0[off], v01 = a0[off + 1];
            float2 v10 = a1[off], v11 = a1[off + 1];
            float tx = v00.x * wx0 + v01.x * fw;
            float bx = v10.x * wx0 + v11.x * fw;
            float ty = v00.y * wx0 + v01.y * fw;
            float by = v10.y * wx0 + v11.y * fw;
            po0[k] = tx * wy0 + bx * fh;
            po1[k] = ty * wy0 + by * fh;
        }
    } else {
        float sfw0 = (w + 0.5f) * INV - 0.5f;
        int   c0f  = (int)floorf(sfw0);
        float2 a0[3], a1[3];
#pragma unroll
        for (int j = 0; j < 3; ++j) {
            int ci = min(max(c0f + j, 0), S - 1);
            a0[j] = r0[ci];
            a1[j] = r1[ci];
        }
#pragma unroll
        for (int k = 0; k < 8; ++k) {
            float sfw = (w + k + 0.5f) * INV - 0.5f;
            int   ifw = (int)floorf(sfw);
            float fw  = sfw - (float)ifw;
            bool  hi  = (ifw != c0f);
            float2 v00 = hi ? a0[1] : a0[0];
            float2 v01 = hi ? a0[2] : a0[1];
            float2 v10 = hi ? a1[1] : a1[0];
            float2 v11 = hi ? a1[2] : a1[1];
            const float wx0 = 1.0f - fw;
            float tx = v00.x * wx0 + v01.x * fw;
            float bx = v10.x * wx0 + v11.x * fw;
            float ty = v00.y * wx0 + v01.y * fw;
            float by = v10.y * wx0 + v11.y * fw;
            po0[k] = tx * wy0 + bx * fh;
            po1[k] = ty * wy0 + by * fh;
        }
    }
    ((float4*)out0)[0] = make_float4(po0[0], po0[1], po0[2], po0[3]);
    ((float4*)out0)[1] = make_float4(po0[4], po0[5], po0[6], po0[7]);
    ((float4*)out1)[0] = make_float4(po1[0], po1[1], po1[2], po1[3]);
    ((float4*)out1)[1] = make_float4(po1[4], po1[5], po1[6], po1[7]);
}

__global__ __launch_bounds__(256) void up_kernel(float* __restrict__ out) {
    const int bl = blockIdx.z;
    const int b  = bl >> 3;               // levels 1..8 per batch
    const int l  = (bl & 7) + 1;
    const int h  = blockIdx.y * 4 + threadIdx.y;

    // smem staging of levels 6 (8x8), 7 (4x4), 8 (2x2, at offset 16).
    __shared__ float2 s78[64];
    if (l >= 6) {
        const int tid = threadIdx.y * 64 + threadIdx.x;
        const float* l5 = g_pyr + c_off[5] + (size_t)b * 16 * 16 * 2;
        if (l == 6) {
            if (tid < 64) s78[tid] = pool2x2(l5, 16, tid >> 3, tid & 7);
        } else {
            if (tid < 16) s78[tid] = pool4x4(l5, 16, tid >> 2, tid & 3);
            if (l == 8) {
                __syncthreads();
                if (tid < 4) {
                    int ih = tid >> 1, iw = tid & 1;
                    float2 q0 = s78[(2 * ih) * 4 + 2 * iw];
                    float2 q1 = s78[(2 * ih) * 4 + 2 * iw + 1];
                    float2 q2 = s78[(2 * ih + 1) * 4 + 2 * iw];
                    float2 q3 = s78[(2 * ih + 1) * 4 + 2 * iw + 1];
                    s78[16 + tid] = make_float2((q0.x + q1.x + q2.x + q3.x) * 0.25f,
                                                (q0.y + q1.y + q2.y + q3.y) * 0.25f);
                }
            }
        }
        __syncthreads();
    }

    const float2* g2 = (const float2*)g_pyr;
    switch (l) {
        case 1: up_body<1>(out, g2 + (c_off[1] >> 1) + (size_t)b * 256 * 256, b, h); break;
        case 2: up_body<2>(out, g2 + (c_off[2] >> 1) + (size_t)b * 128 * 128, b, h); break;
        case 3: up_body<3>(out, g2 + (c_off[3] >> 1) + (size_t)b * 64 * 64, b, h); break;
        case 4: up_body<4>(out, g2 + (c_off[4] >> 1) + (size_t)b * 32 * 32, b, h); break;
        case 5: up_body<5>(out, g2 + (c_off[5] >> 1) + (size_t)b * 16 * 16, b, h); break;
        case 6: up_body<6>(out, s78, b, h); break;
        case 7: up_body<7>(out, s78, b, h); break;
        case 8: up_body<8>(out, s78 + 16, b, h); break;
    }
}

extern "C" void kernel_launch(void* const* d_in, const int* in_sizes, int n_in,
                              void* d_out, int out_size) {
    const float* x = (const float*)d_in[0];
    float* out = (float*)d_out;

    // One kernel: full pyramid (levels 1..5) + level-0 transposed output.
    pool_all_kernel<<<BATCH * 16, 512>>>(x, out);

    // Upsample levels 1..8 (6,7,8 staged in smem from level 5).
    dim3 grid(1, HW / 4, BATCH * 8);
    dim3 block(64, 4);
    up_kernel<<<grid, block>>>(out);
}

// round 17
// speedup vs baseline: 1.7358x; 1.7358x over previous
#include <cuda_runtime.h>
#include <cstddef>

#define BATCH 8
#define HW 512
#define NLEV 9

// Pyramid scratch for levels 1..5 (6,7,8 staged in smem by up), NHWC (C=2).
__device__ __align__(16) float g_pyr[1398080];

// float offsets of level l inside g_pyr; index 0 unused.
__constant__ int c_off[9] = {0, 0, 1048576, 1310720, 1376256, 1392640, 1396736, 1397760, 1398016};

// ---------------------------------------------------------------------------
// pool_all: ONE kernel builds the whole pyramid (levels 1..5) AND emits the
// level-0 transposed output planes. Block = (batch, h-stripe p of 16).
__global__ __launch_bounds__(512) void pool_all_kernel(const float* __restrict__ x,
                                                       float* __restrict__ out) {
    const int p = blockIdx.x & 15;
    const int b = blockIdx.x >> 4;

    // Phase A: input -> level 1 (rows 16p..16p+15), plus level-0 output copy.
    for (int i = threadIdx.x; i < 16 * 128; i += 512) {
        int wp = i & 127;
        int hd = p * 16 + (i >> 7);
        int wd = wp * 2;
        int ws = wd * 2;
        int hs0 = 2 * hd, hs1 = 2 * hd + 1;

        const float4* r0 = (const float4*)(x + ((size_t)(b * HW + hs0) * HW + ws) * 2);
        const float4* r1 = (const float4*)((const float*)r0 + (size_t)HW * 2);
        float4 a0 = r0[0], a1 = r0[1];
        float4 c0 = r1[0], c1 = r1[1];

        float4 pv;
        pv.x = (a0.x + a0.z + c0.x + c0.z) * 0.25f;
        pv.y = (a0.y + a0.w + c0.y + c0.w) * 0.25f;
        pv.z = (a1.x + a1.z + c1.x + c1.z) * 0.25f;
        pv.w = (a1.y + a1.w + c1.y + c1.w) * 0.25f;
        *(float4*)(g_pyr + ((size_t)(b * 256 + hd) * 256 + wd) * 2) = pv;

        float* o00 = out + (((size_t)(b * 2 * NLEV + 0) * HW + hs0) * HW + ws);
        float* o01 = o00 + (size_t)HW;
        float* o10 = out + (((size_t)(b * 2 * NLEV + 1) * HW + hs0) * HW + ws);
        float* o11 = o10 + (size_t)HW;
        *(float4*)o00 = make_float4(a0.x, a0.z, a1.x, a1.z);
        *(float4*)o01 = make_float4(c0.x, c0.z, c1.x, c1.z);
        *(float4*)o10 = make_float4(a0.y, a0.w, a1.y, a1.w);
        *(float4*)o11 = make_float4(c0.y, c0.w, c1.y, c1.w);
    }
    __syncthreads();

    // Phase B: chain levels 1->2->3->4->5 within the stripe.
#pragma unroll
    for (int l = 1; l <= 4; ++l) {
        const int Ss = HW >> l;
        const int Sd = Ss >> 1;
        const int rows = Sd >> 4;
        const float* src = g_pyr + c_off[l]     + (size_t)b * Ss * Ss * 2;
        float*       dst = g_pyr + c_off[l + 1] + (size_t)b * Sd * Sd * 2;
        const int r0 = p * rows;
        const int n = rows * Sd;
        for (int i = threadIdx.x; i < n; i += 512) {
            int wd = i % Sd;
            int hd = r0 + i / Sd;
            float4 a = *(const float4*)(src + ((size_t)(2 * hd) * Ss + 2 * wd) * 2);
            float4 c = *(const float4*)(src + ((size_t)(2 * hd + 1) * Ss + 2 * wd) * 2);
            float2 o;
            o.x = (a.x + a.z + c.x + c.z) * 0.25f;
            o.y = (a.y + a.w + c.y + c.w) * 0.25f;
            *(float2*)(dst + ((size_t)hd * Sd + wd) * 2) = o;
        }
        __syncthreads();
    }
}

// ---------------------------------------------------------------------------
// smem staging helpers: pool from level-5 (16x16, L2-resident broadcast reads)
__device__ __forceinline__ float2 pool2x2(const float* base, int S, int ih, int iw) {
    float4 a = *(const float4*)(base + ((size_t)(2 * ih) * S + 2 * iw) * 2);
    float4 c = *(const float4*)(base + ((size_t)(2 * ih + 1) * S + 2 * iw) * 2);
    return make_float2((a.x + a.z + c.x + c.z) * 0.25f,
                       (a.y + a.w + c.y + c.w) * 0.25f);
}
__device__ __forceinline__ float2 pool4x4(const float* base, int S, int ih, int iw) {
    float sx = 0.f, sy = 0.f;
#pragma unroll
    for (int rr = 0; rr < 4; ++rr) {
        float4 q0 = *(const float4*)(base + ((size_t)(4 * ih + rr) * S + 4 * iw) * 2);
        float4 q1 = *(const float4*)(base + ((size_t)(4 * ih + rr) * S + 4 * iw + 2) * 2);
        sx += q0.x + q0.z + q1.x + q1.z;
        sy += q0.y + q0.w + q1.y + q1.w;
    }
    return make_float2(sx * 0.0625f, sy * 0.0625f);
}

// ---------------------------------------------------------------------------
// up_body: 4 consecutive w outputs per thread, both channels (one float4
// store per channel -> perfectly lane-contiguous warp stores).
// L=1,2: compile-time column-offset/weight tables, deduped loads.
// L>=3: 4 outputs straddle <=2 source columns (generic gather).
template <int L>
__device__ __forceinline__ void up_body(float* __restrict__ out,
                                        const float2* __restrict__ src2,
                                        int b, int h) {
    const int t = threadIdx.x;            // 0..127
    const int w = t * 4;
    float* out0 = out + (((size_t)(b * 2 * NLEV + 2 * L) * HW + h) * HW + w);
    float* out1 = out0 + (size_t)HW * HW;

    constexpr int F = 1 << L;
    constexpr int S = HW >> L;
    constexpr float INV = 1.0f / F;

    float sfh = (h + 0.5f) * INV - 0.5f;
    int   ifh = (int)floorf(sfh);
    float fh  = sfh - (float)ifh;
    int ih0 = min(max(ifh, 0), S - 1);
    int ih1 = min(max(ifh + 1, 0), S - 1);
    const float wy0 = 1.0f - fh;
    const float2* r0 = src2 + (size_t)ih0 * S;
    const float2* r1 = src2 + (size_t)ih1 * S;

    float po0[4];
    float po1[4];

    if constexpr (L <= 2) {
        constexpr int NC = (4 >> L) + 2;       // 4 (L=1) or 3 (L=2)
        constexpr int OFF1[4] = {0,1,1,2};
        constexpr int OFF2[4] = {0,0,1,1};
        constexpr float FW1[4] = {0.75f,0.25f,0.75f,0.25f};
        constexpr float FW2[4] = {0.625f,0.875f,0.125f,0.375f};
        const int c0 = (w >> L) - 1;
        float2 a0[NC], a1[NC];
#pragma unroll
        for (int j = 0; j < NC; ++j) {
            int ci = min(max(c0 + j, 0), S - 1);
            a0[j] = r0[ci];
            a1[j] = r1[ci];
        }
#pragma unroll
        for (int k = 0; k < 4; ++k) {
            const int   off = (L == 1) ? OFF1[k] : OFF2[k];
            const float fw  = (L == 1) ? FW1[k]  : FW2[k];
            const float wx0 = 1.0f - fw;
            float2 v00 = a0[off], v01 = a0[off + 1];
            float2 v10 = a1[off], v11 = a1[off + 1];
            float tx = v00.x * wx0 + v01.x * fw;
            float bx = v10.x * wx0 + v11.x * fw;
            float ty = v00.y * wx0 + v01.y * fw;
            float by = v10.y * wx0 + v11.y * fw;
            po0[k] = tx * wy0 + bx * fh;
            po1[k] = ty * wy0 + by * fh;
        }
    } else {
        // L >= 3: 4 outputs straddle at most 2 source columns
        float sfw0 = (w + 0.5f) * INV - 0.5f;
        int   c0f  = (int)floorf(sfw0);
        float2 a0[3], a1[3];
#pragma unroll
        for (int j = 0; j < 3; ++j) {
            int ci = min(max(c0f + j, 0), S - 1);
            a0[j] = r0[ci];
            a1[j] = r1[ci];
        }
#pragma unroll
        for (int k = 0; k < 4; ++k) {
            float sfw = (w + k + 0.5f) * INV - 0.5f;
            int   ifw = (int)floorf(sfw);
            float fw  = sfw - (float)ifw;
            bool  hi  = (ifw != c0f);
            float2 v00 = hi ? a0[1] : a0[0];
            float2 v01 = hi ? a0[2] : a0[1];
            float2 v10 = hi ? a1[1] : a1[0];
            float2 v11 = hi ? a1[2] : a1[1];
            const float wx0 = 1.0f - fw;
            float tx = v00.x * wx0 + v01.x * fw;
            float bx = v10.x * wx0 + v11.x * fw;
            float ty = v00.y * wx0 + v01.y * fw;
            float by = v10.y * wx0 + v11.y * fw;
            po0[k] = tx * wy0 + bx * fh;
            po1[k] = ty * wy0 + by * fh;
        }
    }
    *(float4*)out0 = make_float4(po0[0], po0[1], po0[2], po0[3]);
    *(float4*)out1 = make_float4(po1[0], po1[1], po1[2], po1[3]);
}

__global__ __launch_bounds__(256) void up_kernel(float* __restrict__ out) {
    const int bl = blockIdx.z;
    const int b  = bl >> 3;               // levels 1..8 per batch
    const int l  = (bl & 7) + 1;
    const int h  = blockIdx.y * 2 + threadIdx.y;

    // smem staging of levels 6 (8x8), 7 (4x4), 8 (2x2, at offset 16).
    __shared__ float2 s78[64];
    if (l >= 6) {
        const int tid = threadIdx.y * 128 + threadIdx.x;
        const float* l5 = g_pyr + c_off[5] + (size_t)b * 16 * 16 * 2;
        if (l == 6) {
            if (tid < 64) s78[tid] = pool2x2(l5, 16, tid >> 3, tid & 7);
        } else {
            if (tid < 16) s78[tid] = pool4x4(l5, 16, tid >> 2, tid & 3);
            if (l == 8) {
                __syncthreads();
                if (tid < 4) {
                    int ih = tid >> 1, iw = tid & 1;
                    float2 q0 = s78[(2 * ih) * 4 + 2 * iw];
                    float2 q1 = s78[(2 * ih) * 4 + 2 * iw + 1];
                    float2 q2 = s78[(2 * ih + 1) * 4 + 2 * iw];
                    float2 q3 = s78[(2 * ih + 1) * 4 + 2 * iw + 1];
                    s78[16 + tid] = make_float2((q0.x + q1.x + q2.x + q3.x) * 0.25f,
                                                (q0.y + q1.y + q2.y + q3.y) * 0.25f);
                }
            }
        }
        __syncthreads();
    }

    const float2* g2 = (const float2*)g_pyr;
    switch (l) {
        case 1: up_body<1>(out, g2 + (c_off[1] >> 1) + (size_t)b * 256 * 256, b, h); break;
        case 2: up_body<2>(out, g2 + (c_off[2] >> 1) + (size_t)b * 128 * 128, b, h); break;
        case 3: up_body<3>(out, g2 + (c_off[3] >> 1) + (size_t)b * 64 * 64, b, h); break;
        case 4: up_body<4>(out, g2 + (c_off[4] >> 1) + (size_t)b * 32 * 32, b, h); break;
        case 5: up_body<5>(out, g2 + (c_off[5] >> 1) + (size_t)b * 16 * 16, b, h); break;
        case 6: up_body<6>(out, s78, b, h); break;
        case 7: up_body<7>(out, s78, b, h); break;
        case 8: up_body<8>(out, s78 + 16, b, h); break;
    }
}

extern "C" void kernel_launch(void* const* d_in, const int* in_sizes, int n_in,
                              void* d_out, int out_size) {
    const float* x = (const float*)d_in[0];
    float* out = (float*)d_out;

    // One kernel: full pyramid (levels 1..5) + level-0 transposed output.
    pool_all_kernel<<<BATCH * 16, 512>>>(x, out);

    // Upsample levels 1..8 (6,7,8 staged in smem from level 5).
    dim3 grid(1, HW / 2, BATCH * 8);
    dim3 block(128, 2);
    up_kernel<<<grid, block>>>(out);
}